// round 12
// baseline (speedup 1.0000x reference)
#include <cuda_runtime.h>
#include <cuda_bf16.h>
#include <cstdint>

#define B_    64
#define S_    1024
#define CIN   5
#define KS    4
#define H1    64
#define H2    16
#define OUTC  32
#define L1    1021
#define C1    22
#define SIGC1 506
#define SC1P  512
#define L2    1018
#define SIGC2 272

// ---- conv2 smem layout: M-tile 256, A halo 259 rows ----
#define APART    37296u                     // 259 * 144
#define ABUF(i)  ((uint32_t)(i) * 74592u)
#define ABUF_LO  APART
#define BBUF(i)  (149184u + (uint32_t)(i) * 18432u)
#define BBUF_LO  9216u
#define DSMB     186048u
// epilogue overlay
#define OFF_Z   0u                 // f32 [256][68]
#define OFF_W1  69632u
#define OFF_W2  86016u
#define OFF_BS  90112u

// ---- scratch ----
__device__ float g_h[B_ * L1 * C1];
__device__ __nv_bfloat16 g_s1h[(size_t)B_ * L1 * SC1P];
__device__ __nv_bfloat16 g_s1l[(size_t)B_ * L1 * SC1P];
__device__ __nv_bfloat16 g_wbh[KS * 64 * SC1P];    // [kk][o][c]
__device__ __nv_bfloat16 g_wbl[KS * 64 * SC1P];
__device__ float g_h2[B_ * L2 * H2];

__device__ __forceinline__ void mma_bf16(
    float& c0, float& c1, float& c2, float& c3,
    uint32_t a0, uint32_t a1, uint32_t a2, uint32_t a3,
    uint32_t b0, uint32_t b1) {
    asm volatile(
        "mma.sync.aligned.m16n8k16.row.col.f32.bf16.bf16.f32 "
        "{%0,%1,%2,%3}, {%4,%5,%6,%7}, {%8,%9}, {%0,%1,%2,%3};"
        : "+f"(c0), "+f"(c1), "+f"(c2), "+f"(c3)
        : "r"(a0), "r"(a1), "r"(a2), "r"(a3), "r"(b0), "r"(b1));
}
__device__ __forceinline__ uint32_t smem_u32(const void* p) {
    uint32_t a;
    asm("{ .reg .u64 t; cvta.to.shared.u64 t, %1; cvt.u32.u64 %0, t; }" : "=r"(a) : "l"(p));
    return a;
}
__device__ __forceinline__ void cp16(uint32_t dst, const void* src, uint32_t sz) {
    asm volatile("cp.async.cg.shared.global [%0], [%1], 16, %2;"
        :: "r"(dst), "l"(src), "r"(sz));
}
__device__ __forceinline__ void cp_commit() { asm volatile("cp.async.commit_group;"); }
__device__ __forceinline__ void cp_wait1()  { asm volatile("cp.async.wait_group 1;" ::: "memory"); }
__device__ __forceinline__ void cp_wait0()  { asm volatile("cp.async.wait_group 0;" ::: "memory"); }
__device__ __forceinline__ void ldm_x4(uint32_t& r0, uint32_t& r1, uint32_t& r2, uint32_t& r3,
                                       uint32_t a) {
    asm volatile("ldmatrix.sync.aligned.m8n8.x4.shared.b16 {%0,%1,%2,%3}, [%4];"
        : "=r"(r0), "=r"(r1), "=r"(r2), "=r"(r3) : "r"(a));
}

// ============================================================
// Repack a2_w0 (O,C,K) -> bf16 hi/lo [kk][o][512c]
// ============================================================
__global__ void k_repack(const float* __restrict__ w0) {
    int idx = blockIdx.x * blockDim.x + threadIdx.x;
    int c  = idx & 511;
    int o  = (idx >> 9) & 63;
    int kk = idx >> 15;
    float v = (c < SIGC1) ? w0[(o * SIGC1 + c) * KS + kk] : 0.f;
    __nv_bfloat16 hi = __float2bfloat16(v);
    __nv_bfloat16 lo = __float2bfloat16(v - __bfloat162float(hi));
    g_wbh[idx] = hi;
    g_wbl[idx] = lo;
}

// ============================================================
// Augment 1
// ============================================================
__global__ __launch_bounds__(128) void k_aug1(
    const float* __restrict__ x,
    const float* __restrict__ w0, const float* __restrict__ b0,
    const float* __restrict__ w1, const float* __restrict__ b1,
    const float* __restrict__ w2, const float* __restrict__ b2)
{
    __shared__ float w0s[H1*CIN*KS], w1s[H1*H1], w2s[H2*H1];
    __shared__ float b0s[H1], b1s[H1], b2s[H2];
    int tid = threadIdx.x;
    for (int i = tid; i < H1*CIN*KS; i += 128) w0s[i] = w0[i];
    for (int i = tid; i < H1*H1;     i += 128) w1s[i] = w1[i];
    for (int i = tid; i < H2*H1;     i += 128) w2s[i] = w2[i];
    if (tid < H1) { b0s[tid] = b0[tid]; b1s[tid] = b1[tid]; }
    if (tid < H2) b2s[tid] = b2[tid];
    __syncthreads();

    int b = blockIdx.y;
    int t = blockIdx.x * 128 + tid;
    if (t >= L1) return;

    float xr[KS][CIN];
#pragma unroll
    for (int k = 0; k < KS; k++)
#pragma unroll
        for (int c = 0; c < CIN; c++)
            xr[k][c] = x[((size_t)(b * S_) + t + k) * CIN + c];

    float z1[H1];
#pragma unroll
    for (int o = 0; o < H1; o++) {
        float s = b0s[o];
#pragma unroll
        for (int c = 0; c < CIN; c++)
#pragma unroll
            for (int k = 0; k < KS; k++)
                s += w0s[(o*CIN + c)*KS + k] * xr[k][c];
        z1[o] = fmaxf(s, 0.f);
    }
    float z3[H2];
#pragma unroll
    for (int o = 0; o < H2; o++) z3[o] = b2s[o];
    for (int o2 = 0; o2 < H1; o2++) {
        float s = b1s[o2];
#pragma unroll
        for (int c = 0; c < H1; c++) s += w1s[o2*H1 + c] * z1[c];
        s = fmaxf(s, 0.f);
#pragma unroll
        for (int o = 0; o < H2; o++) z3[o] += w2s[o*H1 + o2] * s;
    }
    float* hrow = &g_h[(size_t)(b * L1 + t) * C1];
#pragma unroll
    for (int c = 0; c < CIN; c++) hrow[c] = xr[KS-1][c];
    hrow[CIN] = (float)t * (1.0f / (float)(L1 - 1));
#pragma unroll
    for (int o = 0; o < H2; o++) hrow[CIN + 1 + o] = z3[o];
}

// ============================================================
// Sig1: fused scan (one CTA per batch), writes s1 bf16 hi/lo
// ============================================================
__device__ __forceinline__ void store_hl(size_t base, int ch, float v) {
    __nv_bfloat16 hi = __float2bfloat16(v);
    __nv_bfloat16 lo = __float2bfloat16(v - __bfloat162float(hi));
    g_s1h[base + ch] = hi;
    g_s1l[base + ch] = lo;
}

__global__ __launch_bounds__(512) void k_sig1() {
    __shared__ float hs[129][C1];
    int b = blockIdx.x, tid = threadIdx.x;
    int i = tid / C1, j = tid - i * C1;       // valid for tid < 484
    size_t base = (size_t)b * L1 * SC1P;
    float acc = 0.f;
    for (int c0 = 0; c0 < L1; c0 += 128) {
        for (int idx = tid; idx < 129 * C1; idx += 512) {
            int r = idx / C1, c = idx - r * C1;
            int row = c0 - 1 + r;
            hs[r][c] = (row >= 0 && row < L1) ? g_h[((size_t)b * L1 + row) * C1 + c] : 0.f;
        }
        __syncthreads();
        int tend = min(c0 + 128, L1);
        if (tid < C1 * C1) {
            for (int t = c0; t < tend; t++) {
                int r = t - c0 + 1;
                float hpi = hs[r-1][i], hpj = hs[r-1][j];
                float dxi = hs[r][i] - hpi, dxj = hs[r][j] - hpj;
                acc += hpi * dxj + 0.5f * dxi * dxj;
                store_hl(base + (size_t)t * SC1P, C1 + tid, acc);
            }
        } else {
            int ch = (tid < C1 * C1 + C1) ? (tid - C1 * C1) : tid;
            for (int t = c0; t < tend; t++) {
                int r = t - c0 + 1;
                float v = (tid < C1 * C1 + C1) ? hs[r][tid - C1 * C1] : 0.f;
                store_hl(base + (size_t)t * SC1P, ch, v);
            }
        }
        __syncthreads();
    }
}

// ============================================================
// Conv stack 2: split-bf16 HMMA, M-tile 256, cp.async pipeline,
// ldmatrix fragments, fused epilogue
// ============================================================
__global__ __launch_bounds__(256, 1) void k_conv2_mma(
    const float* __restrict__ b0,
    const float* __restrict__ w1, const float* __restrict__ b1,
    const float* __restrict__ w2, const float* __restrict__ b2)
{
    extern __shared__ __align__(16) char dsm[];
    uint32_t sb = smem_u32(dsm);
    int tid = threadIdx.x;
    int lane = tid & 31, wid = tid >> 5;
    int warp_m = wid & 3, warp_n = wid >> 2;
    int b = blockIdx.y, t0 = blockIdx.x * 256;
    int g = lane >> 2, t4 = lane & 3;

    float C[4][4][4];
#pragma unroll
    for (int mt = 0; mt < 4; mt++)
#pragma unroll
        for (int nt = 0; nt < 4; nt++)
#pragma unroll
            for (int q = 0; q < 4; q++) C[mt][nt][q] = 0.f;

    const __nv_bfloat16* gAh = g_s1h + (size_t)b * L1 * SC1P;
    const __nv_bfloat16* gAl = g_s1l + (size_t)b * L1 * SC1P;

    uint32_t aoff = (uint32_t)((lane & 15) * 144 + (lane >> 4) * 16);
    int q = lane >> 3, rr = lane & 7;
    uint32_t boff = (uint32_t)((((q >> 1) * 8) + rr) * 144 + (q & 1) * 16);

#define ISSUE_A(cb_, abuf_) do {                                            \
        int cbb_ = (cb_) << 6;                                              \
        _Pragma("unroll")                                                   \
        for (int it = 0; it < 9; it++) {                                    \
            int idx_ = tid + it * 256;                                      \
            if (idx_ < 259 * 8) {                                           \
                int row_ = idx_ >> 3, g8_ = idx_ & 7;                       \
                int t_ = t0 + row_;                                         \
                uint32_t sz_ = (t_ < L1) ? 16u : 0u;                        \
                int tc_ = (t_ < L1) ? t_ : (L1 - 1);                        \
                uint32_t d_ = sb + (abuf_) + (uint32_t)(row_ * 144 + g8_ * 16); \
                cp16(d_, gAh + (size_t)tc_ * SC1P + cbb_ + g8_ * 8, sz_);   \
                cp16(d_ + ABUF_LO, gAl + (size_t)tc_ * SC1P + cbb_ + g8_ * 8, sz_); \
            }                                                               \
        }                                                                   \
    } while (0)

#define ISSUE_B(ph_, bbuf_) do {                                            \
        int cb_ = (ph_) >> 2, kk_ = (ph_) & 3;                              \
        int cbb_ = cb_ << 6;                                                \
        _Pragma("unroll")                                                   \
        for (int it = 0; it < 2; it++) {                                    \
            int idx_ = tid + it * 256;                                      \
            int o_ = idx_ >> 3, g8_ = idx_ & 7;                             \
            uint32_t d_ = sb + (bbuf_) + (uint32_t)(o_ * 144 + g8_ * 16);   \
            cp16(d_, g_wbh + (size_t)(kk_ * 64 + o_) * SC1P + cbb_ + g8_ * 8, 16u); \
            cp16(d_ + BBUF_LO, g_wbl + (size_t)(kk_ * 64 + o_) * SC1P + cbb_ + g8_ * 8, 16u); \
        }                                                                   \
    } while (0)

    ISSUE_A(0, ABUF(0));
    ISSUE_B(0, BBUF(0));
    cp_commit();

    for (int p = 0; p < 32; p++) {
        int cb = p >> 2, kk = p & 3;
        if (p < 31) {
            int pn = p + 1;
            if ((pn & 3) == 0) ISSUE_A(pn >> 2, ABUF((pn >> 2) & 1));
            ISSUE_B(pn, BBUF(pn & 1));
            cp_commit();
            cp_wait1();
        } else {
            cp_wait0();
        }
        __syncthreads();

        uint32_t Ah = sb + ABUF(cb & 1) + (uint32_t)((kk + warp_m * 64) * 144) + aoff;
        uint32_t Bb = sb + BBUF(p & 1) + (uint32_t)(warp_n * 32 * 144) + boff;
#pragma unroll
        for (int ks = 0; ks < 4; ks++) {
            uint32_t ko = (uint32_t)(ks * 32);
            uint32_t ah[4][4], al[4][4], bh[4][2], bl[4][2];
#pragma unroll
            for (int mt = 0; mt < 4; mt++) {
                ldm_x4(ah[mt][0], ah[mt][1], ah[mt][2], ah[mt][3],
                       Ah + (uint32_t)(mt * 16 * 144) + ko);
                ldm_x4(al[mt][0], al[mt][1], al[mt][2], al[mt][3],
                       Ah + ABUF_LO + (uint32_t)(mt * 16 * 144) + ko);
            }
#pragma unroll
            for (int j = 0; j < 2; j++) {
                ldm_x4(bh[2*j][0], bh[2*j][1], bh[2*j+1][0], bh[2*j+1][1],
                       Bb + (uint32_t)(j * 16 * 144) + ko);
                ldm_x4(bl[2*j][0], bl[2*j][1], bl[2*j+1][0], bl[2*j+1][1],
                       Bb + BBUF_LO + (uint32_t)(j * 16 * 144) + ko);
            }
#pragma unroll
            for (int mt = 0; mt < 4; mt++)
#pragma unroll
                for (int nt = 0; nt < 4; nt++) {
                    float* c = C[mt][nt];
                    mma_bf16(c[0], c[1], c[2], c[3],
                             ah[mt][0], ah[mt][1], ah[mt][2], ah[mt][3],
                             bh[nt][0], bh[nt][1]);
                    mma_bf16(c[0], c[1], c[2], c[3],
                             ah[mt][0], ah[mt][1], ah[mt][2], ah[mt][3],
                             bl[nt][0], bl[nt][1]);
                    mma_bf16(c[0], c[1], c[2], c[3],
                             al[mt][0], al[mt][1], al[mt][2], al[mt][3],
                             bh[nt][0], bh[nt][1]);
                }
        }
        __syncthreads();
    }

    // ---- epilogue: C -> Z[256][68] f32 ----
#pragma unroll
    for (int mt = 0; mt < 4; mt++)
#pragma unroll
        for (int nt = 0; nt < 4; nt++) {
            int row = warp_m * 64 + mt * 16 + g;
            int col = warp_n * 32 + nt * 8 + 2 * t4;
            *(float2*)(dsm + OFF_Z + row * 272 + col * 4) =
                make_float2(C[mt][nt][0], C[mt][nt][1]);
            *(float2*)(dsm + OFF_Z + (row + 8) * 272 + col * 4) =
                make_float2(C[mt][nt][2], C[mt][nt][3]);
        }
    float* W1t = (float*)(dsm + OFF_W1);
    float* W2s = (float*)(dsm + OFF_W2);
    float* bss = (float*)(dsm + OFF_BS);
#pragma unroll
    for (int qq = 0; qq < 16; qq++) {
        int idx = tid + qq * 256;
        W1t[(idx & 63) * 64 + (idx >> 6)] = w1[idx];
    }
#pragma unroll
    for (int qq = 0; qq < 4; qq++) {
        int idx = tid + qq * 256;
        W2s[idx] = w2[idx];
    }
    if (tid < 64) { bss[tid] = b0[tid]; bss[64 + tid] = b1[tid]; }
    if (tid < 16) bss[128 + tid] = b2[tid];
    __syncthreads();

#pragma unroll
    for (int pass = 0; pass < 2; pass++) {
        int row = (tid >> 1) + pass * 128;
        int half = tid & 1;
        int o2b = half * 32;
        float z2[32];
#pragma unroll
        for (int o = 0; o < 32; o++) z2[o] = bss[64 + o2b + o];
#pragma unroll 4
        for (int c = 0; c < 64; c++) {
            float zc = fmaxf(*(const float*)(dsm + OFF_Z + row * 272 + c * 4) + bss[c], 0.f);
            const float4* wv = (const float4*)&W1t[c * 64 + o2b];
#pragma unroll
            for (int q8 = 0; q8 < 8; q8++) {
                float4 w4 = wv[q8];
                z2[q8*4+0] += zc * w4.x; z2[q8*4+1] += zc * w4.y;
                z2[q8*4+2] += zc * w4.z; z2[q8*4+3] += zc * w4.w;
            }
        }
#pragma unroll
        for (int o = 0; o < 32; o++) z2[o] = fmaxf(z2[o], 0.f);

        float pv[16];
#pragma unroll
        for (int o3 = 0; o3 < 16; o3++) {
            float s = 0.f;
            const float4* wv = (const float4*)&W2s[o3 * 64 + o2b];
#pragma unroll
            for (int q8 = 0; q8 < 8; q8++) {
                float4 w4 = wv[q8];
                s += w4.x * z2[q8*4+0] + w4.y * z2[q8*4+1]
                   + w4.z * z2[q8*4+2] + w4.w * z2[q8*4+3];
            }
            pv[o3] = s;
        }
#pragma unroll
        for (int o3 = 0; o3 < 16; o3++)
            pv[o3] += __shfl_xor_sync(0xffffffffu, pv[o3], 1);

        int t = t0 + row;
        if (t < L2) {
            int ob = half * 8;
            float4 v0 = make_float4(pv[ob+0] + bss[128+ob+0], pv[ob+1] + bss[128+ob+1],
                                    pv[ob+2] + bss[128+ob+2], pv[ob+3] + bss[128+ob+3]);
            float4 v1 = make_float4(pv[ob+4] + bss[128+ob+4], pv[ob+5] + bss[128+ob+5],
                                    pv[ob+6] + bss[128+ob+6], pv[ob+7] + bss[128+ob+7]);
            float* dst = &g_h2[(size_t)(b * L2 + t) * H2 + ob];
            *(float4*)dst = v0;
            *(float4*)(dst + 4) = v1;
        }
    }
}

// ============================================================
// become_constant + sig2 + linear
// ============================================================
__global__ __launch_bounds__(256) void k_sig2(
    const int* __restrict__ lengths,
    const float* __restrict__ lw, const float* __restrict__ lb,
    float* __restrict__ out)
{
    __shared__ float hs[129][16];
    __shared__ float s2s[SIGC2];
    int b = blockIdx.x, tid = threadIdx.x;
    int adj = lengths[b] - 2 * KS + 2;
    if (adj < 1) adj = 1;
    if (adj > L2) adj = L2;
    int i = tid >> 4, j = tid & 15;
    float acc = 0.f;
    for (int c0 = 0; c0 < adj; c0 += 128) {
        for (int idx = tid; idx < 129 * 16; idx += 256) {
            int r = idx >> 4, c = idx & 15;
            int row = c0 - 1 + r;
            hs[r][c] = (row >= 0 && row < L2) ? g_h2[(size_t)(b * L2 + row) * H2 + c] : 0.f;
        }
        __syncthreads();
        int tend = min(c0 + 128, adj);
        for (int t = c0; t < tend; t++) {
            int r = t - c0 + 1;
            float hpi = hs[r-1][i], hpj = hs[r-1][j];
            float dxi = hs[r][i] - hpi, dxj = hs[r][j] - hpj;
            acc += hpi * dxj + 0.5f * dxi * dxj;
        }
        __syncthreads();
    }
    s2s[16 + tid] = acc;
    if (tid < 16) s2s[tid] = g_h2[(size_t)(b * L2 + adj - 1) * H2 + tid];
    __syncthreads();
    if (tid < OUTC) {
        float v = lb[tid];
        for (int c = 0; c < SIGC2; c++) v += lw[tid * SIGC2 + c] * s2s[c];
        out[b * OUTC + tid] = v;
    }
}

// ============================================================
extern "C" void kernel_launch(void* const* d_in, const int* in_sizes, int n_in,
                              void* d_out, int out_size) {
    const float* x      = (const float*)d_in[0];
    const int*   lens   = (const int*)  d_in[1];
    const float* a1_w0  = (const float*)d_in[2];
    const float* a1_b0  = (const float*)d_in[3];
    const float* a1_w1  = (const float*)d_in[4];
    const float* a1_b1  = (const float*)d_in[5];
    const float* a1_w2  = (const float*)d_in[6];
    const float* a1_b2  = (const float*)d_in[7];
    const float* a2_w0  = (const float*)d_in[8];
    const float* a2_b0  = (const float*)d_in[9];
    const float* a2_w1  = (const float*)d_in[10];
    const float* a2_b1  = (const float*)d_in[11];
    const float* a2_w2  = (const float*)d_in[12];
    const float* a2_b2  = (const float*)d_in[13];
    const float* lin_w  = (const float*)d_in[14];
    const float* lin_b  = (const float*)d_in[15];
    float* out = (float*)d_out;

    static bool attr_set = false;
    if (!attr_set) {
        cudaFuncSetAttribute(k_conv2_mma, cudaFuncAttributeMaxDynamicSharedMemorySize, DSMB);
        attr_set = true;
    }

    k_repack<<<512, 256>>>(a2_w0);
    k_aug1<<<dim3(8, B_), 128>>>(x, a1_w0, a1_b0, a1_w1, a1_b1, a1_w2, a1_b2);
    k_sig1<<<B_, 512>>>();
    k_conv2_mma<<<dim3(4, B_), 256, DSMB>>>(a2_b0, a2_w1, a2_b1, a2_w2, a2_b2);
    k_sig2<<<B_, 256>>>(lens, lin_w, lin_b, out);
}

// round 13
// speedup vs baseline: 1.1758x; 1.1758x over previous
#include <cuda_runtime.h>
#include <cuda_bf16.h>
#include <cstdint>

#define B_    64
#define S_    1024
#define CIN   5
#define KS    4
#define H1    64
#define H2    16
#define OUTC  32
#define L1    1021
#define C1    22
#define SIGC1 506
#define SC1P  512
#define L2    1018
#define SIGC2 272
#define NC1   16
#define CH1   64

// ---- conv2 smem layout: M-tile 256, 512 threads ----
#define APART    37296u                     // 259 * 144
#define ABUF(i)  ((uint32_t)(i) * 74592u)
#define ABUF_LO  APART
#define BBUF(i)  (149184u + (uint32_t)(i) * 18432u)
#define BBUF_LO  9216u
#define DSMB     186048u
// epilogue overlay
#define OFF_Z   0u                 // f32 [256][68]
#define OFF_W1  69632u
#define OFF_W2  86016u
#define OFF_BS  90112u

// ---- scratch ----
__device__ float g_h[B_ * L1 * C1];
__device__ __nv_bfloat16 g_s1h[(size_t)B_ * L1 * SC1P];
__device__ __nv_bfloat16 g_s1l[(size_t)B_ * L1 * SC1P];
__device__ __nv_bfloat16 g_wbh[KS * 64 * SC1P];    // [kk][o][c]
__device__ __nv_bfloat16 g_wbl[KS * 64 * SC1P];
__device__ float g_csum[B_ * NC1 * SC1P];
__device__ float g_h2[B_ * L2 * H2];

__device__ __forceinline__ void mma_bf16(
    float& c0, float& c1, float& c2, float& c3,
    uint32_t a0, uint32_t a1, uint32_t a2, uint32_t a3,
    uint32_t b0, uint32_t b1) {
    asm volatile(
        "mma.sync.aligned.m16n8k16.row.col.f32.bf16.bf16.f32 "
        "{%0,%1,%2,%3}, {%4,%5,%6,%7}, {%8,%9}, {%0,%1,%2,%3};"
        : "+f"(c0), "+f"(c1), "+f"(c2), "+f"(c3)
        : "r"(a0), "r"(a1), "r"(a2), "r"(a3), "r"(b0), "r"(b1));
}
__device__ __forceinline__ uint32_t smem_u32(const void* p) {
    uint32_t a;
    asm("{ .reg .u64 t; cvta.to.shared.u64 t, %1; cvt.u32.u64 %0, t; }" : "=r"(a) : "l"(p));
    return a;
}
__device__ __forceinline__ void cp16(uint32_t dst, const void* src, uint32_t sz) {
    asm volatile("cp.async.cg.shared.global [%0], [%1], 16, %2;"
        :: "r"(dst), "l"(src), "r"(sz));
}
__device__ __forceinline__ void cp_commit() { asm volatile("cp.async.commit_group;"); }
__device__ __forceinline__ void cp_wait1()  { asm volatile("cp.async.wait_group 1;" ::: "memory"); }
__device__ __forceinline__ void cp_wait0()  { asm volatile("cp.async.wait_group 0;" ::: "memory"); }
__device__ __forceinline__ void ldm_x4(uint32_t& r0, uint32_t& r1, uint32_t& r2, uint32_t& r3,
                                       uint32_t a) {
    asm volatile("ldmatrix.sync.aligned.m8n8.x4.shared.b16 {%0,%1,%2,%3}, [%4];"
        : "=r"(r0), "=r"(r1), "=r"(r2), "=r"(r3) : "r"(a));
}

// ============================================================
// Repack a2_w0 (O,C,K) -> bf16 hi/lo [kk][o][512c]
// ============================================================
__global__ void k_repack(const float* __restrict__ w0) {
    int idx = blockIdx.x * blockDim.x + threadIdx.x;
    int c  = idx & 511;
    int o  = (idx >> 9) & 63;
    int kk = idx >> 15;
    float v = (c < SIGC1) ? w0[(o * SIGC1 + c) * KS + kk] : 0.f;
    __nv_bfloat16 hi = __float2bfloat16(v);
    __nv_bfloat16 lo = __float2bfloat16(v - __bfloat162float(hi));
    g_wbh[idx] = hi;
    g_wbl[idx] = lo;
}

// ============================================================
// Augment 1
// ============================================================
__global__ __launch_bounds__(128) void k_aug1(
    const float* __restrict__ x,
    const float* __restrict__ w0, const float* __restrict__ b0,
    const float* __restrict__ w1, const float* __restrict__ b1,
    const float* __restrict__ w2, const float* __restrict__ b2)
{
    __shared__ float w0s[H1*CIN*KS], w1s[H1*H1], w2s[H2*H1];
    __shared__ float b0s[H1], b1s[H1], b2s[H2];
    int tid = threadIdx.x;
    for (int i = tid; i < H1*CIN*KS; i += 128) w0s[i] = w0[i];
    for (int i = tid; i < H1*H1;     i += 128) w1s[i] = w1[i];
    for (int i = tid; i < H2*H1;     i += 128) w2s[i] = w2[i];
    if (tid < H1) { b0s[tid] = b0[tid]; b1s[tid] = b1[tid]; }
    if (tid < H2) b2s[tid] = b2[tid];
    __syncthreads();

    int b = blockIdx.y;
    int t = blockIdx.x * 128 + tid;
    if (t >= L1) return;

    float xr[KS][CIN];
#pragma unroll
    for (int k = 0; k < KS; k++)
#pragma unroll
        for (int c = 0; c < CIN; c++)
            xr[k][c] = x[((size_t)(b * S_) + t + k) * CIN + c];

    float z1[H1];
#pragma unroll
    for (int o = 0; o < H1; o++) {
        float s = b0s[o];
#pragma unroll
        for (int c = 0; c < CIN; c++)
#pragma unroll
            for (int k = 0; k < KS; k++)
                s += w0s[(o*CIN + c)*KS + k] * xr[k][c];
        z1[o] = fmaxf(s, 0.f);
    }
    float z3[H2];
#pragma unroll
    for (int o = 0; o < H2; o++) z3[o] = b2s[o];
    for (int o2 = 0; o2 < H1; o2++) {
        float s = b1s[o2];
#pragma unroll
        for (int c = 0; c < H1; c++) s += w1s[o2*H1 + c] * z1[c];
        s = fmaxf(s, 0.f);
#pragma unroll
        for (int o = 0; o < H2; o++) z3[o] += w2s[o*H1 + o2] * s;
    }
    float* hrow = &g_h[(size_t)(b * L1 + t) * C1];
#pragma unroll
    for (int c = 0; c < CIN; c++) hrow[c] = xr[KS-1][c];
    hrow[CIN] = (float)t * (1.0f / (float)(L1 - 1));
#pragma unroll
    for (int o = 0; o < H2; o++) hrow[CIN + 1 + o] = z3[o];
}

// ============================================================
// Sig1: 3-pass parallel scan (R11 version)
// ============================================================
__global__ __launch_bounds__(512) void k_sig1_sum() {
    __shared__ float hs[CH1 + 1][C1];
    int b = blockIdx.y, nc = blockIdx.x, tid = threadIdx.x;
    int c0 = nc * CH1;
    for (int idx = tid; idx < (CH1 + 1) * C1; idx += 512) {
        int r = idx / C1, c = idx - r * C1;
        int row = c0 - 1 + r;
        hs[r][c] = (row >= 0 && row < L1) ? g_h[(size_t)(b * L1 + row) * C1 + c] : 0.f;
    }
    __syncthreads();
    if (tid >= C1 * C1) return;
    int i = tid / C1, j = tid - i * C1;
    float acc = 0.f;
    int tend = min(c0 + CH1, L1);
    for (int t = c0; t < tend; t++) {
        int r = t - c0 + 1;
        float hpi = hs[r-1][i], hpj = hs[r-1][j];
        float dxi = hs[r][i] - hpi, dxj = hs[r][j] - hpj;
        acc += hpi * dxj + 0.5f * dxi * dxj;
    }
    g_csum[(b * NC1 + nc) * SC1P + tid] = acc;
}

__global__ void k_sig1_prefix() {
    int b = blockIdx.x, tid = threadIdx.x;
    if (tid >= C1 * C1) return;
    float run = 0.f;
    for (int nc = 0; nc < NC1; nc++) {
        int idx = (b * NC1 + nc) * SC1P + tid;
        float v = g_csum[idx];
        g_csum[idx] = run;
        run += v;
    }
}

__device__ __forceinline__ void store_hl(size_t base, int ch, float v) {
    __nv_bfloat16 hi = __float2bfloat16(v);
    __nv_bfloat16 lo = __float2bfloat16(v - __bfloat162float(hi));
    g_s1h[base + ch] = hi;
    g_s1l[base + ch] = lo;
}

__global__ __launch_bounds__(512) void k_sig1_write() {
    __shared__ float hs[CH1 + 1][C1];
    int b = blockIdx.y, nc = blockIdx.x, tid = threadIdx.x;
    int c0 = nc * CH1;
    for (int idx = tid; idx < (CH1 + 1) * C1; idx += 512) {
        int r = idx / C1, c = idx - r * C1;
        int row = c0 - 1 + r;
        hs[r][c] = (row >= 0 && row < L1) ? g_h[(size_t)(b * L1 + row) * C1 + c] : 0.f;
    }
    __syncthreads();
    int tend = min(c0 + CH1, L1);
    if (tid < C1 * C1) {
        int i = tid / C1, j = tid - i * C1;
        float acc = g_csum[(b * NC1 + nc) * SC1P + tid];
        for (int t = c0; t < tend; t++) {
            int r = t - c0 + 1;
            float hpi = hs[r-1][i], hpj = hs[r-1][j];
            float dxi = hs[r][i] - hpi, dxj = hs[r][j] - hpj;
            acc += hpi * dxj + 0.5f * dxi * dxj;
            store_hl((size_t)(b * L1 + t) * SC1P, C1 + tid, acc);
        }
    } else {
        int c = tid - C1 * C1;
        int ch = (c < C1) ? c : (C1 * C1 + c);
        for (int t = c0; t < tend; t++) {
            int r = t - c0 + 1;
            float v = (c < C1) ? hs[r][c] : 0.f;
            store_hl((size_t)(b * L1 + t) * SC1P, ch, v);
        }
    }
}

// ============================================================
// Conv stack 2: split-bf16 HMMA, M-tile 256 @ 512 threads,
// cp.async pipeline, ldmatrix fragments, fused epilogue
// 16 warps: warp_m = wid&7 (32 rows each), warp_n = wid>>3 (32 cols)
// ============================================================
__global__ __launch_bounds__(512, 1) void k_conv2_mma(
    const float* __restrict__ b0,
    const float* __restrict__ w1, const float* __restrict__ b1,
    const float* __restrict__ w2, const float* __restrict__ b2)
{
    extern __shared__ __align__(16) char dsm[];
    uint32_t sb = smem_u32(dsm);
    int tid = threadIdx.x;
    int lane = tid & 31, wid = tid >> 5;
    int warp_m = wid & 7, warp_n = wid >> 3;
    int b = blockIdx.y, t0 = blockIdx.x * 256;
    int g = lane >> 2, t4 = lane & 3;

    float C[2][4][4];
#pragma unroll
    for (int mt = 0; mt < 2; mt++)
#pragma unroll
        for (int nt = 0; nt < 4; nt++)
#pragma unroll
            for (int q = 0; q < 4; q++) C[mt][nt][q] = 0.f;

    const __nv_bfloat16* gAh = g_s1h + (size_t)b * L1 * SC1P;
    const __nv_bfloat16* gAl = g_s1l + (size_t)b * L1 * SC1P;

    uint32_t aoff = (uint32_t)((lane & 15) * 144 + (lane >> 4) * 16);
    int q = lane >> 3, rr = lane & 7;
    uint32_t boff = (uint32_t)((((q >> 1) * 8) + rr) * 144 + (q & 1) * 16);

#define ISSUE_A(cb_, abuf_) do {                                            \
        int cbb_ = (cb_) << 6;                                              \
        _Pragma("unroll")                                                   \
        for (int it = 0; it < 5; it++) {                                    \
            int idx_ = tid + it * 512;                                      \
            if (idx_ < 259 * 8) {                                           \
                int row_ = idx_ >> 3, g8_ = idx_ & 7;                       \
                int t_ = t0 + row_;                                         \
                uint32_t sz_ = (t_ < L1) ? 16u : 0u;                        \
                int tc_ = (t_ < L1) ? t_ : (L1 - 1);                        \
                uint32_t d_ = sb + (abuf_) + (uint32_t)(row_ * 144 + g8_ * 16); \
                cp16(d_, gAh + (size_t)tc_ * SC1P + cbb_ + g8_ * 8, sz_);   \
                cp16(d_ + ABUF_LO, gAl + (size_t)tc_ * SC1P + cbb_ + g8_ * 8, sz_); \
            }                                                               \
        }                                                                   \
    } while (0)

#define ISSUE_B(ph_, bbuf_) do {                                            \
        int cb_ = (ph_) >> 2, kk_ = (ph_) & 3;                              \
        int cbb_ = cb_ << 6;                                                \
        {                                                                   \
            int o_ = tid >> 3, g8_ = tid & 7;                               \
            uint32_t d_ = sb + (bbuf_) + (uint32_t)(o_ * 144 + g8_ * 16);   \
            cp16(d_, g_wbh + (size_t)(kk_ * 64 + o_) * SC1P + cbb_ + g8_ * 8, 16u); \
            cp16(d_ + BBUF_LO, g_wbl + (size_t)(kk_ * 64 + o_) * SC1P + cbb_ + g8_ * 8, 16u); \
        }                                                                   \
    } while (0)

    ISSUE_A(0, ABUF(0));
    ISSUE_B(0, BBUF(0));
    cp_commit();

    for (int p = 0; p < 32; p++) {
        int cb = p >> 2, kk = p & 3;
        if (p < 31) {
            int pn = p + 1;
            if ((pn & 3) == 0) ISSUE_A(pn >> 2, ABUF((pn >> 2) & 1));
            ISSUE_B(pn, BBUF(pn & 1));
            cp_commit();
            cp_wait1();
        } else {
            cp_wait0();
        }
        __syncthreads();

        uint32_t Ah = sb + ABUF(cb & 1) + (uint32_t)((kk + warp_m * 32) * 144) + aoff;
        uint32_t Bb = sb + BBUF(p & 1) + (uint32_t)(warp_n * 32 * 144) + boff;
#pragma unroll
        for (int ks = 0; ks < 4; ks++) {
            uint32_t ko = (uint32_t)(ks * 32);
            uint32_t ah[2][4], al[2][4], bh[4][2], bl[4][2];
#pragma unroll
            for (int mt = 0; mt < 2; mt++) {
                ldm_x4(ah[mt][0], ah[mt][1], ah[mt][2], ah[mt][3],
                       Ah + (uint32_t)(mt * 16 * 144) + ko);
                ldm_x4(al[mt][0], al[mt][1], al[mt][2], al[mt][3],
                       Ah + ABUF_LO + (uint32_t)(mt * 16 * 144) + ko);
            }
#pragma unroll
            for (int j = 0; j < 2; j++) {
                ldm_x4(bh[2*j][0], bh[2*j][1], bh[2*j+1][0], bh[2*j+1][1],
                       Bb + (uint32_t)(j * 16 * 144) + ko);
                ldm_x4(bl[2*j][0], bl[2*j][1], bl[2*j+1][0], bl[2*j+1][1],
                       Bb + BBUF_LO + (uint32_t)(j * 16 * 144) + ko);
            }
#pragma unroll
            for (int mt = 0; mt < 2; mt++)
#pragma unroll
                for (int nt = 0; nt < 4; nt++) {
                    float* c = C[mt][nt];
                    mma_bf16(c[0], c[1], c[2], c[3],
                             ah[mt][0], ah[mt][1], ah[mt][2], ah[mt][3],
                             bh[nt][0], bh[nt][1]);
                    mma_bf16(c[0], c[1], c[2], c[3],
                             ah[mt][0], ah[mt][1], ah[mt][2], ah[mt][3],
                             bl[nt][0], bl[nt][1]);
                    mma_bf16(c[0], c[1], c[2], c[3],
                             al[mt][0], al[mt][1], al[mt][2], al[mt][3],
                             bh[nt][0], bh[nt][1]);
                }
        }
        __syncthreads();
    }

    // ---- epilogue: C -> Z[256][68] f32 ----
#pragma unroll
    for (int mt = 0; mt < 2; mt++)
#pragma unroll
        for (int nt = 0; nt < 4; nt++) {
            int row = warp_m * 32 + mt * 16 + g;
            int col = warp_n * 32 + nt * 8 + 2 * t4;
            *(float2*)(dsm + OFF_Z + row * 272 + col * 4) =
                make_float2(C[mt][nt][0], C[mt][nt][1]);
            *(float2*)(dsm + OFF_Z + (row + 8) * 272 + col * 4) =
                make_float2(C[mt][nt][2], C[mt][nt][3]);
        }
    float* W1t = (float*)(dsm + OFF_W1);
    float* W2s = (float*)(dsm + OFF_W2);
    float* bss = (float*)(dsm + OFF_BS);
#pragma unroll
    for (int qq = 0; qq < 8; qq++) {
        int idx = tid + qq * 512;
        W1t[(idx & 63) * 64 + (idx >> 6)] = w1[idx];
    }
#pragma unroll
    for (int qq = 0; qq < 2; qq++) {
        int idx = tid + qq * 512;
        W2s[idx] = w2[idx];
    }
    if (tid < 64) { bss[tid] = b0[tid]; bss[64 + tid] = b1[tid]; }
    if (tid < 16) bss[128 + tid] = b2[tid];
    __syncthreads();

    {
        int row = tid >> 1, half = tid & 1;
        int o2b = half * 32;
        float z2[32];
#pragma unroll
        for (int o = 0; o < 32; o++) z2[o] = bss[64 + o2b + o];
#pragma unroll 4
        for (int c = 0; c < 64; c++) {
            float zc = fmaxf(*(const float*)(dsm + OFF_Z + row * 272 + c * 4) + bss[c], 0.f);
            const float4* wv = (const float4*)&W1t[c * 64 + o2b];
#pragma unroll
            for (int q8 = 0; q8 < 8; q8++) {
                float4 w4 = wv[q8];
                z2[q8*4+0] += zc * w4.x; z2[q8*4+1] += zc * w4.y;
                z2[q8*4+2] += zc * w4.z; z2[q8*4+3] += zc * w4.w;
            }
        }
#pragma unroll
        for (int o = 0; o < 32; o++) z2[o] = fmaxf(z2[o], 0.f);

        float pv[16];
#pragma unroll
        for (int o3 = 0; o3 < 16; o3++) {
            float s = 0.f;
            const float4* wv = (const float4*)&W2s[o3 * 64 + o2b];
#pragma unroll
            for (int q8 = 0; q8 < 8; q8++) {
                float4 w4 = wv[q8];
                s += w4.x * z2[q8*4+0] + w4.y * z2[q8*4+1]
                   + w4.z * z2[q8*4+2] + w4.w * z2[q8*4+3];
            }
            pv[o3] = s;
        }
#pragma unroll
        for (int o3 = 0; o3 < 16; o3++)
            pv[o3] += __shfl_xor_sync(0xffffffffu, pv[o3], 1);

        int t = t0 + row;
        if (t < L2) {
            int ob = half * 8;
            float4 v0 = make_float4(pv[ob+0] + bss[128+ob+0], pv[ob+1] + bss[128+ob+1],
                                    pv[ob+2] + bss[128+ob+2], pv[ob+3] + bss[128+ob+3]);
            float4 v1 = make_float4(pv[ob+4] + bss[128+ob+4], pv[ob+5] + bss[128+ob+5],
                                    pv[ob+6] + bss[128+ob+6], pv[ob+7] + bss[128+ob+7]);
            float* dst = &g_h2[(size_t)(b * L2 + t) * H2 + ob];
            *(float4*)dst = v0;
            *(float4*)(dst + 4) = v1;
        }
    }
}

// ============================================================
// become_constant + sig2 + linear
// ============================================================
__global__ __launch_bounds__(256) void k_sig2(
    const int* __restrict__ lengths,
    const float* __restrict__ lw, const float* __restrict__ lb,
    float* __restrict__ out)
{
    __shared__ float hs[129][16];
    __shared__ float s2s[SIGC2];
    int b = blockIdx.x, tid = threadIdx.x;
    int adj = lengths[b] - 2 * KS + 2;
    if (adj < 1) adj = 1;
    if (adj > L2) adj = L2;
    int i = tid >> 4, j = tid & 15;
    float acc = 0.f;
    for (int c0 = 0; c0 < adj; c0 += 128) {
        for (int idx = tid; idx < 129 * 16; idx += 256) {
            int r = idx >> 4, c = idx & 15;
            int row = c0 - 1 + r;
            hs[r][c] = (row >= 0 && row < L2) ? g_h2[(size_t)(b * L2 + row) * H2 + c] : 0.f;
        }
        __syncthreads();
        int tend = min(c0 + 128, adj);
        for (int t = c0; t < tend; t++) {
            int r = t - c0 + 1;
            float hpi = hs[r-1][i], hpj = hs[r-1][j];
            float dxi = hs[r][i] - hpi, dxj = hs[r][j] - hpj;
            acc += hpi * dxj + 0.5f * dxi * dxj;
        }
        __syncthreads();
    }
    s2s[16 + tid] = acc;
    if (tid < 16) s2s[tid] = g_h2[(size_t)(b * L2 + adj - 1) * H2 + tid];
    __syncthreads();
    if (tid < OUTC) {
        float v = lb[tid];
        for (int c = 0; c < SIGC2; c++) v += lw[tid * SIGC2 + c] * s2s[c];
        out[b * OUTC + tid] = v;
    }
}

// ============================================================
extern "C" void kernel_launch(void* const* d_in, const int* in_sizes, int n_in,
                              void* d_out, int out_size) {
    const float* x      = (const float*)d_in[0];
    const int*   lens   = (const int*)  d_in[1];
    const float* a1_w0  = (const float*)d_in[2];
    const float* a1_b0  = (const float*)d_in[3];
    const float* a1_w1  = (const float*)d_in[4];
    const float* a1_b1  = (const float*)d_in[5];
    const float* a1_w2  = (const float*)d_in[6];
    const float* a1_b2  = (const float*)d_in[7];
    const float* a2_w0  = (const float*)d_in[8];
    const float* a2_b0  = (const float*)d_in[9];
    const float* a2_w1  = (const float*)d_in[10];
    const float* a2_b1  = (const float*)d_in[11];
    const float* a2_w2  = (const float*)d_in[12];
    const float* a2_b2  = (const float*)d_in[13];
    const float* lin_w  = (const float*)d_in[14];
    const float* lin_b  = (const float*)d_in[15];
    float* out = (float*)d_out;

    static bool attr_set = false;
    if (!attr_set) {
        cudaFuncSetAttribute(k_conv2_mma, cudaFuncAttributeMaxDynamicSharedMemorySize, DSMB);
        attr_set = true;
    }

    k_repack<<<512, 256>>>(a2_w0);
    k_aug1<<<dim3(8, B_), 128>>>(x, a1_w0, a1_b0, a1_w1, a1_b1, a1_w2, a1_b2);
    k_sig1_sum<<<dim3(NC1, B_), 512>>>();
    k_sig1_prefix<<<B_, 512>>>();
    k_sig1_write<<<dim3(NC1, B_), 512>>>();
    k_conv2_mma<<<dim3(4, B_), 512, DSMB>>>(a2_b0, a2_w1, a2_b1, a2_w2, a2_b2);
    k_sig2<<<B_, 256>>>(lens, lin_w, lin_b, out);
}

// round 14
// speedup vs baseline: 1.1822x; 1.0055x over previous
#include <cuda_runtime.h>
#include <cuda_bf16.h>
#include <cstdint>

#define B_    64
#define S_    1024
#define CIN   5
#define KS    4
#define H1    64
#define H2    16
#define OUTC  32
#define L1    1021
#define C1    22
#define SIGC1 506
#define SC1P  512
#define L2    1018
#define SIGC2 272
#define NC1   16
#define CH1   64

// ---- conv2 smem layout (double-buffered A and B), TM=128, 256 thr ----
#define ABUF(i)  ((uint32_t)(i) * 37728u)   // 131 rows x 144B, hi+lo
#define ABUF_LO  18864u
#define BBUF(i)  (75456u + (uint32_t)(i) * 18432u)
#define BBUF_LO  9216u
#define DSMB     112320u
// epilogue overlay
#define OFF_Z   0u                 // f32 [128][68]
#define OFF_W1  36864u
#define OFF_W2  53248u
#define OFF_BS  57344u

// ---- scratch ----
__device__ float g_h[B_ * L1 * C1];
__device__ __nv_bfloat16 g_s1h[(size_t)B_ * L1 * SC1P];
__device__ __nv_bfloat16 g_s1l[(size_t)B_ * L1 * SC1P];
__device__ __nv_bfloat16 g_wbh[KS * 64 * SC1P];    // [kk][o][c]
__device__ __nv_bfloat16 g_wbl[KS * 64 * SC1P];
__device__ float g_csum[B_ * NC1 * SC1P];
__device__ float g_h2[B_ * L2 * H2];

__device__ __forceinline__ void mma_bf16(
    float& c0, float& c1, float& c2, float& c3,
    uint32_t a0, uint32_t a1, uint32_t a2, uint32_t a3,
    uint32_t b0, uint32_t b1) {
    asm volatile(
        "mma.sync.aligned.m16n8k16.row.col.f32.bf16.bf16.f32 "
        "{%0,%1,%2,%3}, {%4,%5,%6,%7}, {%8,%9}, {%0,%1,%2,%3};"
        : "+f"(c0), "+f"(c1), "+f"(c2), "+f"(c3)
        : "r"(a0), "r"(a1), "r"(a2), "r"(a3), "r"(b0), "r"(b1));
}
__device__ __forceinline__ uint32_t smem_u32(const void* p) {
    uint32_t a;
    asm("{ .reg .u64 t; cvta.to.shared.u64 t, %1; cvt.u32.u64 %0, t; }" : "=r"(a) : "l"(p));
    return a;
}
__device__ __forceinline__ void cp16(uint32_t dst, const void* src, uint32_t sz) {
    asm volatile("cp.async.cg.shared.global [%0], [%1], 16, %2;"
        :: "r"(dst), "l"(src), "r"(sz));
}
__device__ __forceinline__ void cp_commit() { asm volatile("cp.async.commit_group;"); }
__device__ __forceinline__ void cp_wait1()  { asm volatile("cp.async.wait_group 1;" ::: "memory"); }
__device__ __forceinline__ void cp_wait0()  { asm volatile("cp.async.wait_group 0;" ::: "memory"); }
__device__ __forceinline__ void ldm_x4(uint32_t& r0, uint32_t& r1, uint32_t& r2, uint32_t& r3,
                                       uint32_t a) {
    asm volatile("ldmatrix.sync.aligned.m8n8.x4.shared.b16 {%0,%1,%2,%3}, [%4];"
        : "=r"(r0), "=r"(r1), "=r"(r2), "=r"(r3) : "r"(a));
}

// ============================================================
// Repack a2_w0 (O,C,K) -> bf16 hi/lo [kk][o][512c]
// ============================================================
__global__ void k_repack(const float* __restrict__ w0) {
    int idx = blockIdx.x * blockDim.x + threadIdx.x;
    int c  = idx & 511;
    int o  = (idx >> 9) & 63;
    int kk = idx >> 15;
    float v = (c < SIGC1) ? w0[(o * SIGC1 + c) * KS + kk] : 0.f;
    __nv_bfloat16 hi = __float2bfloat16(v);
    __nv_bfloat16 lo = __float2bfloat16(v - __bfloat162float(hi));
    g_wbh[idx] = hi;
    g_wbl[idx] = lo;
}

// ============================================================
// Augment 1
// ============================================================
__global__ __launch_bounds__(128) void k_aug1(
    const float* __restrict__ x,
    const float* __restrict__ w0, const float* __restrict__ b0,
    const float* __restrict__ w1, const float* __restrict__ b1,
    const float* __restrict__ w2, const float* __restrict__ b2)
{
    __shared__ float w0s[H1*CIN*KS], w1s[H1*H1], w2s[H2*H1];
    __shared__ float b0s[H1], b1s[H1], b2s[H2];
    int tid = threadIdx.x;
    for (int i = tid; i < H1*CIN*KS; i += 128) w0s[i] = w0[i];
    for (int i = tid; i < H1*H1;     i += 128) w1s[i] = w1[i];
    for (int i = tid; i < H2*H1;     i += 128) w2s[i] = w2[i];
    if (tid < H1) { b0s[tid] = b0[tid]; b1s[tid] = b1[tid]; }
    if (tid < H2) b2s[tid] = b2[tid];
    __syncthreads();

    int b = blockIdx.y;
    int t = blockIdx.x * 128 + tid;
    if (t >= L1) return;

    float xr[KS][CIN];
#pragma unroll
    for (int k = 0; k < KS; k++)
#pragma unroll
        for (int c = 0; c < CIN; c++)
            xr[k][c] = x[((size_t)(b * S_) + t + k) * CIN + c];

    float z1[H1];
#pragma unroll
    for (int o = 0; o < H1; o++) {
        float s = b0s[o];
#pragma unroll
        for (int c = 0; c < CIN; c++)
#pragma unroll
            for (int k = 0; k < KS; k++)
                s += w0s[(o*CIN + c)*KS + k] * xr[k][c];
        z1[o] = fmaxf(s, 0.f);
    }
    float z3[H2];
#pragma unroll
    for (int o = 0; o < H2; o++) z3[o] = b2s[o];
    for (int o2 = 0; o2 < H1; o2++) {
        float s = b1s[o2];
#pragma unroll
        for (int c = 0; c < H1; c++) s += w1s[o2*H1 + c] * z1[c];
        s = fmaxf(s, 0.f);
#pragma unroll
        for (int o = 0; o < H2; o++) z3[o] += w2s[o*H1 + o2] * s;
    }
    float* hrow = &g_h[(size_t)(b * L1 + t) * C1];
#pragma unroll
    for (int c = 0; c < CIN; c++) hrow[c] = xr[KS-1][c];
    hrow[CIN] = (float)t * (1.0f / (float)(L1 - 1));
#pragma unroll
    for (int o = 0; o < H2; o++) hrow[CIN + 1 + o] = z3[o];
}

// ============================================================
// Sig1 passes (3-pass parallel scan)
// ============================================================
__global__ __launch_bounds__(512) void k_sig1_sum() {
    __shared__ float hs[CH1 + 1][C1];
    int b = blockIdx.y, nc = blockIdx.x, tid = threadIdx.x;
    int c0 = nc * CH1;
    for (int idx = tid; idx < (CH1 + 1) * C1; idx += 512) {
        int r = idx / C1, c = idx - r * C1;
        int row = c0 - 1 + r;
        hs[r][c] = (row >= 0 && row < L1) ? g_h[(size_t)(b * L1 + row) * C1 + c] : 0.f;
    }
    __syncthreads();
    if (tid >= C1 * C1) return;
    int i = tid / C1, j = tid - i * C1;
    float acc = 0.f;
    int tend = min(c0 + CH1, L1);
    for (int t = c0; t < tend; t++) {
        int r = t - c0 + 1;
        float hpi = hs[r-1][i], hpj = hs[r-1][j];
        float dxi = hs[r][i] - hpi, dxj = hs[r][j] - hpj;
        acc += hpi * dxj + 0.5f * dxi * dxj;
    }
    g_csum[(b * NC1 + nc) * SC1P + tid] = acc;
}

__global__ void k_sig1_prefix() {
    int b = blockIdx.x, tid = threadIdx.x;
    if (tid >= C1 * C1) return;
    float run = 0.f;
    for (int nc = 0; nc < NC1; nc++) {
        int idx = (b * NC1 + nc) * SC1P + tid;
        float v = g_csum[idx];
        g_csum[idx] = run;
        run += v;
    }
}

__device__ __forceinline__ void store_hl(size_t base, int ch, float v) {
    __nv_bfloat16 hi = __float2bfloat16(v);
    __nv_bfloat16 lo = __float2bfloat16(v - __bfloat162float(hi));
    g_s1h[base + ch] = hi;
    g_s1l[base + ch] = lo;
}

__global__ __launch_bounds__(512) void k_sig1_write() {
    __shared__ float hs[CH1 + 1][C1];
    int b = blockIdx.y, nc = blockIdx.x, tid = threadIdx.x;
    int c0 = nc * CH1;
    for (int idx = tid; idx < (CH1 + 1) * C1; idx += 512) {
        int r = idx / C1, c = idx - r * C1;
        int row = c0 - 1 + r;
        hs[r][c] = (row >= 0 && row < L1) ? g_h[(size_t)(b * L1 + row) * C1 + c] : 0.f;
    }
    __syncthreads();
    int tend = min(c0 + CH1, L1);
    if (tid < C1 * C1) {
        int i = tid / C1, j = tid - i * C1;
        float acc = g_csum[(b * NC1 + nc) * SC1P + tid];
        for (int t = c0; t < tend; t++) {
            int r = t - c0 + 1;
            float hpi = hs[r-1][i], hpj = hs[r-1][j];
            float dxi = hs[r][i] - hpi, dxj = hs[r][j] - hpj;
            acc += hpi * dxj + 0.5f * dxi * dxj;
            store_hl((size_t)(b * L1 + t) * SC1P, C1 + tid, acc);
        }
    } else {
        int c = tid - C1 * C1;
        int ch = (c < C1) ? c : (C1 * C1 + c);
        for (int t = c0; t < tend; t++) {
            int r = t - c0 + 1;
            float v = (c < C1) ? hs[r][c] : 0.f;
            store_hl((size_t)(b * L1 + t) * SC1P, ch, v);
        }
    }
}

// ============================================================
// Conv stack 2: split-bf16 HMMA, cp.async pipeline with A-halo
// issue spread across phases, ldmatrix fragments, fused epilogue
// ============================================================
__global__ __launch_bounds__(256, 2) void k_conv2_mma(
    const float* __restrict__ b0,
    const float* __restrict__ w1, const float* __restrict__ b1,
    const float* __restrict__ w2, const float* __restrict__ b2)
{
    extern __shared__ __align__(16) char dsm[];
    uint32_t sb = smem_u32(dsm);
    int tid = threadIdx.x;
    int lane = tid & 31, wid = tid >> 5;
    int warp_m = wid & 3, warp_n = wid >> 2;
    int b = blockIdx.y, t0 = blockIdx.x * 128;
    int g = lane >> 2, t4 = lane & 3;

    float C[2][4][4];
#pragma unroll
    for (int mt = 0; mt < 2; mt++)
#pragma unroll
        for (int nt = 0; nt < 4; nt++)
#pragma unroll
            for (int q = 0; q < 4; q++) C[mt][nt][q] = 0.f;

    const __nv_bfloat16* gAh = g_s1h + (size_t)b * L1 * SC1P;
    const __nv_bfloat16* gAl = g_s1l + (size_t)b * L1 * SC1P;

    uint32_t aoff = (uint32_t)((lane & 15) * 144 + (lane >> 4) * 16);
    int q = lane >> 3, rr = lane & 7;
    uint32_t boff = (uint32_t)((((q >> 1) * 8) + rr) * 144 + (q & 1) * 16);

    // A issue, elements [start, end) of the 1048 (131 rows x 8 groups)
#define ISSUE_A_RANGE(cb_, abuf_, start_, end_) do {                        \
        int cbb_ = (cb_) << 6;                                              \
        for (int idx_ = tid + (start_); idx_ < (end_); idx_ += 256) {       \
            int row_ = idx_ >> 3, g8_ = idx_ & 7;                           \
            int t_ = t0 + row_;                                             \
            uint32_t sz_ = (t_ < L1) ? 16u : 0u;                            \
            int tc_ = (t_ < L1) ? t_ : (L1 - 1);                            \
            uint32_t d_ = sb + (abuf_) + (uint32_t)(row_ * 144 + g8_ * 16); \
            cp16(d_, gAh + (size_t)tc_ * SC1P + cbb_ + g8_ * 8, sz_);       \
            cp16(d_ + ABUF_LO, gAl + (size_t)tc_ * SC1P + cbb_ + g8_ * 8, sz_); \
        }                                                                   \
    } while (0)

#define ISSUE_B(ph_, bbuf_) do {                                            \
        int cbB_ = (ph_) >> 2, kkB_ = (ph_) & 3;                            \
        int cbbB_ = cbB_ << 6;                                              \
        _Pragma("unroll")                                                   \
        for (int it = 0; it < 2; it++) {                                    \
            int idx_ = tid + it * 256;                                      \
            int o_ = idx_ >> 3, g8_ = idx_ & 7;                             \
            uint32_t d_ = sb + (bbuf_) + (uint32_t)(o_ * 144 + g8_ * 16);   \
            cp16(d_, g_wbh + (size_t)(kkB_ * 64 + o_) * SC1P + cbbB_ + g8_ * 8, 16u); \
            cp16(d_ + BBUF_LO, g_wbl + (size_t)(kkB_ * 64 + o_) * SC1P + cbbB_ + g8_ * 8, 16u); \
        }                                                                   \
    } while (0)

    // prologue: full A(0) + B(0)
    ISSUE_A_RANGE(0, ABUF(0), 0, 1048);
    ISSUE_B(0, BBUF(0));
    cp_commit();

    for (int p = 0; p < 32; p++) {
        int cb = p >> 2, kk = p & 3;
        if (p < 31) {
            // spread next cblock's A over phases 4c..4c+2 (q=0,1,2)
            if (kk < 3 && cb < 7) {
                int st = kk * 352;
                int en = st + 352; if (en > 1048) en = 1048;
                ISSUE_A_RANGE(cb + 1, ABUF((cb + 1) & 1), st, en);
            }
            ISSUE_B(p + 1, BBUF((p + 1) & 1));
            cp_commit();
            cp_wait1();
        } else {
            cp_wait0();
        }
        __syncthreads();

        uint32_t Ah = sb + ABUF(cb & 1) + (uint32_t)((kk + warp_m * 32) * 144) + aoff;
        uint32_t Bb = sb + BBUF(p & 1) + (uint32_t)(warp_n * 32 * 144) + boff;
#pragma unroll
        for (int ks = 0; ks < 4; ks++) {
            uint32_t ko = (uint32_t)(ks * 32);
            uint32_t ah[2][4], al[2][4], bh[4][2], bl[4][2];
#pragma unroll
            for (int mt = 0; mt < 2; mt++) {
                ldm_x4(ah[mt][0], ah[mt][1], ah[mt][2], ah[mt][3],
                       Ah + (uint32_t)(mt * 16 * 144) + ko);
                ldm_x4(al[mt][0], al[mt][1], al[mt][2], al[mt][3],
                       Ah + ABUF_LO + (uint32_t)(mt * 16 * 144) + ko);
            }
#pragma unroll
            for (int j = 0; j < 2; j++) {
                ldm_x4(bh[2*j][0], bh[2*j][1], bh[2*j+1][0], bh[2*j+1][1],
                       Bb + (uint32_t)(j * 16 * 144) + ko);
                ldm_x4(bl[2*j][0], bl[2*j][1], bl[2*j+1][0], bl[2*j+1][1],
                       Bb + BBUF_LO + (uint32_t)(j * 16 * 144) + ko);
            }
#pragma unroll
            for (int mt = 0; mt < 2; mt++)
#pragma unroll
                for (int nt = 0; nt < 4; nt++) {
                    float* c = C[mt][nt];
                    mma_bf16(c[0], c[1], c[2], c[3],
                             ah[mt][0], ah[mt][1], ah[mt][2], ah[mt][3],
                             bh[nt][0], bh[nt][1]);
                    mma_bf16(c[0], c[1], c[2], c[3],
                             ah[mt][0], ah[mt][1], ah[mt][2], ah[mt][3],
                             bl[nt][0], bl[nt][1]);
                    mma_bf16(c[0], c[1], c[2], c[3],
                             al[mt][0], al[mt][1], al[mt][2], al[mt][3],
                             bh[nt][0], bh[nt][1]);
                }
        }
        __syncthreads();
    }

    // ---- epilogue ----
#pragma unroll
    for (int mt = 0; mt < 2; mt++)
#pragma unroll
        for (int nt = 0; nt < 4; nt++) {
            int row = warp_m * 32 + mt * 16 + g;
            int col = warp_n * 32 + nt * 8 + 2 * t4;
            *(float2*)(dsm + OFF_Z + row * 272 + col * 4) =
                make_float2(C[mt][nt][0], C[mt][nt][1]);
            *(float2*)(dsm + OFF_Z + (row + 8) * 272 + col * 4) =
                make_float2(C[mt][nt][2], C[mt][nt][3]);
        }
    float* W1t = (float*)(dsm + OFF_W1);
    float* W2s = (float*)(dsm + OFF_W2);
    float* bss = (float*)(dsm + OFF_BS);
#pragma unroll
    for (int qq = 0; qq < 16; qq++) {
        int idx = tid + qq * 256;
        W1t[(idx & 63) * 64 + (idx >> 6)] = w1[idx];
    }
#pragma unroll
    for (int qq = 0; qq < 4; qq++) {
        int idx = tid + qq * 256;
        W2s[idx] = w2[idx];
    }
    if (tid < 64) { bss[tid] = b0[tid]; bss[64 + tid] = b1[tid]; }
    if (tid < 16) bss[128 + tid] = b2[tid];
    __syncthreads();

    int row = tid >> 1, half = tid & 1;
    int o2b = half * 32;
    float z2[32];
#pragma unroll
    for (int o = 0; o < 32; o++) z2[o] = bss[64 + o2b + o];
#pragma unroll 4
    for (int c = 0; c < 64; c++) {
        float zc = fmaxf(*(const float*)(dsm + OFF_Z + row * 272 + c * 4) + bss[c], 0.f);
        const float4* wv = (const float4*)&W1t[c * 64 + o2b];
#pragma unroll
        for (int q8 = 0; q8 < 8; q8++) {
            float4 w4 = wv[q8];
            z2[q8*4+0] += zc * w4.x; z2[q8*4+1] += zc * w4.y;
            z2[q8*4+2] += zc * w4.z; z2[q8*4+3] += zc * w4.w;
        }
    }
#pragma unroll
    for (int o = 0; o < 32; o++) z2[o] = fmaxf(z2[o], 0.f);

    float pv[16];
#pragma unroll
    for (int o3 = 0; o3 < 16; o3++) {
        float s = 0.f;
        const float4* wv = (const float4*)&W2s[o3 * 64 + o2b];
#pragma unroll
        for (int q8 = 0; q8 < 8; q8++) {
            float4 w4 = wv[q8];
            s += w4.x * z2[q8*4+0] + w4.y * z2[q8*4+1]
               + w4.z * z2[q8*4+2] + w4.w * z2[q8*4+3];
        }
        pv[o3] = s;
    }
#pragma unroll
    for (int o3 = 0; o3 < 16; o3++)
        pv[o3] += __shfl_xor_sync(0xffffffffu, pv[o3], 1);

    int t = t0 + row;
    if (t < L2) {
        int ob = half * 8;
        float4 v0 = make_float4(pv[ob+0] + bss[128+ob+0], pv[ob+1] + bss[128+ob+1],
                                pv[ob+2] + bss[128+ob+2], pv[ob+3] + bss[128+ob+3]);
        float4 v1 = make_float4(pv[ob+4] + bss[128+ob+4], pv[ob+5] + bss[128+ob+5],
                                pv[ob+6] + bss[128+ob+6], pv[ob+7] + bss[128+ob+7]);
        float* dst = &g_h2[(size_t)(b * L2 + t) * H2 + ob];
        *(float4*)dst = v0;
        *(float4*)(dst + 4) = v1;
    }
}

// ============================================================
// become_constant + sig2 + linear
// ============================================================
__global__ __launch_bounds__(256) void k_sig2(
    const int* __restrict__ lengths,
    const float* __restrict__ lw, const float* __restrict__ lb,
    float* __restrict__ out)
{
    __shared__ float hs[129][16];
    __shared__ float s2s[SIGC2];
    int b = blockIdx.x, tid = threadIdx.x;
    int adj = lengths[b] - 2 * KS + 2;
    if (adj < 1) adj = 1;
    if (adj > L2) adj = L2;
    int i = tid >> 4, j = tid & 15;
    float acc = 0.f;
    for (int c0 = 0; c0 < adj; c0 += 128) {
        for (int idx = tid; idx < 129 * 16; idx += 256) {
            int r = idx >> 4, c = idx & 15;
            int row = c0 - 1 + r;
            hs[r][c] = (row >= 0 && row < L2) ? g_h2[(size_t)(b * L2 + row) * H2 + c] : 0.f;
        }
        __syncthreads();
        int tend = min(c0 + 128, adj);
        for (int t = c0; t < tend; t++) {
            int r = t - c0 + 1;
            float hpi = hs[r-1][i], hpj = hs[r-1][j];
            float dxi = hs[r][i] - hpi, dxj = hs[r][j] - hpj;
            acc += hpi * dxj + 0.5f * dxi * dxj;
        }
        __syncthreads();
    }
    s2s[16 + tid] = acc;
    if (tid < 16) s2s[tid] = g_h2[(size_t)(b * L2 + adj - 1) * H2 + tid];
    __syncthreads();
    if (tid < OUTC) {
        float v = lb[tid];
        for (int c = 0; c < SIGC2; c++) v += lw[tid * SIGC2 + c] * s2s[c];
        out[b * OUTC + tid] = v;
    }
}

// ============================================================
extern "C" void kernel_launch(void* const* d_in, const int* in_sizes, int n_in,
                              void* d_out, int out_size) {
    const float* x      = (const float*)d_in[0];
    const int*   lens   = (const int*)  d_in[1];
    const float* a1_w0  = (const float*)d_in[2];
    const float* a1_b0  = (const float*)d_in[3];
    const float* a1_w1  = (const float*)d_in[4];
    const float* a1_b1  = (const float*)d_in[5];
    const float* a1_w2  = (const float*)d_in[6];
    const float* a1_b2  = (const float*)d_in[7];
    const float* a2_w0  = (const float*)d_in[8];
    const float* a2_b0  = (const float*)d_in[9];
    const float* a2_w1  = (const float*)d_in[10];
    const float* a2_b1  = (const float*)d_in[11];
    const float* a2_w2  = (const float*)d_in[12];
    const float* a2_b2  = (const float*)d_in[13];
    const float* lin_w  = (const float*)d_in[14];
    const float* lin_b  = (const float*)d_in[15];
    float* out = (float*)d_out;

    static bool attr_set = false;
    if (!attr_set) {
        cudaFuncSetAttribute(k_conv2_mma, cudaFuncAttributeMaxDynamicSharedMemorySize, DSMB);
        attr_set = true;
    }

    k_repack<<<512, 256>>>(a2_w0);
    k_aug1<<<dim3(8, B_), 128>>>(x, a1_w0, a1_b0, a1_w1, a1_b1, a1_w2, a1_b2);
    k_sig1_sum<<<dim3(NC1, B_), 512>>>();
    k_sig1_prefix<<<B_, 512>>>();
    k_sig1_write<<<dim3(NC1, B_), 512>>>();
    k_conv2_mma<<<dim3(8, B_), 256, DSMB>>>(a2_b0, a2_w1, a2_b1, a2_w2, a2_b2);
    k_sig2<<<B_, 256>>>(lens, lin_w, lin_b, out);
}

// round 16
// speedup vs baseline: 1.2040x; 1.0185x over previous
#include <cuda_runtime.h>
#include <cuda_bf16.h>
#include <cstdint>

#define B_    64
#define S_    1024
#define CIN   5
#define KS    4
#define H1    64
#define H2    16
#define OUTC  32
#define L1    1021
#define C1    22
#define SIGC1 506
#define SC1P  512
#define L2    1018
#define SIGC2 272
#define NC1   16
#define CH1   64

// ---- conv2 smem layout: A single buf (scan-filled), B double buf, H rows ----
#define OFF_A    0u                 // 131 rows x 144B hi + same lo
#define ABUF_LO  18864u
#define BBUF(i)  (37728u + (uint32_t)(i) * 18432u)
#define BBUF_LO  9216u
#define OFF_H    74592u             // 132 x 22 fp32 = 11616 B
#define DSMB     86208u
// epilogue overlay (reuses A/B space after mainloop)
#define OFF_Z   0u                  // f32 [128][68]
#define OFF_W1  36864u
#define OFF_W2  53248u
#define OFF_BS  57344u

// ---- scratch ----
__device__ float g_h[B_ * L1 * C1];
__device__ __nv_bfloat16 g_wbh[KS * 64 * SC1P];    // [kk][o][c]
__device__ __nv_bfloat16 g_wbl[KS * 64 * SC1P];
__device__ float g_csum[B_ * NC1 * SC1P];
__device__ float g_h2[B_ * L2 * H2];

__device__ __forceinline__ void mma_bf16(
    float& c0, float& c1, float& c2, float& c3,
    uint32_t a0, uint32_t a1, uint32_t a2, uint32_t a3,
    uint32_t b0, uint32_t b1) {
    asm volatile(
        "mma.sync.aligned.m16n8k16.row.col.f32.bf16.bf16.f32 "
        "{%0,%1,%2,%3}, {%4,%5,%6,%7}, {%8,%9}, {%0,%1,%2,%3};"
        : "+f"(c0), "+f"(c1), "+f"(c2), "+f"(c3)
        : "r"(a0), "r"(a1), "r"(a2), "r"(a3), "r"(b0), "r"(b1));
}
__device__ __forceinline__ uint32_t smem_u32(const void* p) {
    uint32_t a;
    asm("{ .reg .u64 t; cvta.to.shared.u64 t, %1; cvt.u32.u64 %0, t; }" : "=r"(a) : "l"(p));
    return a;
}
__device__ __forceinline__ void cp16(uint32_t dst, const void* src, uint32_t sz) {
    asm volatile("cp.async.cg.shared.global [%0], [%1], 16, %2;"
        :: "r"(dst), "l"(src), "r"(sz));
}
__device__ __forceinline__ void cp_commit() { asm volatile("cp.async.commit_group;"); }
__device__ __forceinline__ void cp_wait1()  { asm volatile("cp.async.wait_group 1;" ::: "memory"); }
__device__ __forceinline__ void cp_wait0()  { asm volatile("cp.async.wait_group 0;" ::: "memory"); }
__device__ __forceinline__ void ldm_x4(uint32_t& r0, uint32_t& r1, uint32_t& r2, uint32_t& r3,
                                       uint32_t a) {
    asm volatile("ldmatrix.sync.aligned.m8n8.x4.shared.b16 {%0,%1,%2,%3}, [%4];"
        : "=r"(r0), "=r"(r1), "=r"(r2), "=r"(r3) : "r"(a));
}

// ============================================================
// Repack a2_w0 (O,C,K) -> bf16 hi/lo [kk][o][512c]
// ============================================================
__global__ void k_repack(const float* __restrict__ w0) {
    int idx = blockIdx.x * blockDim.x + threadIdx.x;
    int c  = idx & 511;
    int o  = (idx >> 9) & 63;
    int kk = idx >> 15;
    float v = (c < SIGC1) ? w0[(o * SIGC1 + c) * KS + kk] : 0.f;
    __nv_bfloat16 hi = __float2bfloat16(v);
    __nv_bfloat16 lo = __float2bfloat16(v - __bfloat162float(hi));
    g_wbh[idx] = hi;
    g_wbl[idx] = lo;
}

// ============================================================
// Augment 1
// ============================================================
__global__ __launch_bounds__(128) void k_aug1(
    const float* __restrict__ x,
    const float* __restrict__ w0, const float* __restrict__ b0,
    const float* __restrict__ w1, const float* __restrict__ b1,
    const float* __restrict__ w2, const float* __restrict__ b2)
{
    __shared__ float w0s[H1*CIN*KS], w1s[H1*H1], w2s[H2*H1];
    __shared__ float b0s[H1], b1s[H1], b2s[H2];
    int tid = threadIdx.x;
    for (int i = tid; i < H1*CIN*KS; i += 128) w0s[i] = w0[i];
    for (int i = tid; i < H1*H1;     i += 128) w1s[i] = w1[i];
    for (int i = tid; i < H2*H1;     i += 128) w2s[i] = w2[i];
    if (tid < H1) { b0s[tid] = b0[tid]; b1s[tid] = b1[tid]; }
    if (tid < H2) b2s[tid] = b2[tid];
    __syncthreads();

    int b = blockIdx.y;
    int t = blockIdx.x * 128 + tid;
    if (t >= L1) return;

    float xr[KS][CIN];
#pragma unroll
    for (int k = 0; k < KS; k++)
#pragma unroll
        for (int c = 0; c < CIN; c++)
            xr[k][c] = x[((size_t)(b * S_) + t + k) * CIN + c];

    float z1[H1];
#pragma unroll
    for (int o = 0; o < H1; o++) {
        float s = b0s[o];
#pragma unroll
        for (int c = 0; c < CIN; c++)
#pragma unroll
            for (int k = 0; k < KS; k++)
                s += w0s[(o*CIN + c)*KS + k] * xr[k][c];
        z1[o] = fmaxf(s, 0.f);
    }
    float z3[H2];
#pragma unroll
    for (int o = 0; o < H2; o++) z3[o] = b2s[o];
    for (int o2 = 0; o2 < H1; o2++) {
        float s = b1s[o2];
#pragma unroll
        for (int c = 0; c < H1; c++) s += w1s[o2*H1 + c] * z1[c];
        s = fmaxf(s, 0.f);
#pragma unroll
        for (int o = 0; o < H2; o++) z3[o] += w2s[o*H1 + o2] * s;
    }
    float* hrow = &g_h[(size_t)(b * L1 + t) * C1];
#pragma unroll
    for (int c = 0; c < CIN; c++) hrow[c] = xr[KS-1][c];
    hrow[CIN] = (float)t * (1.0f / (float)(L1 - 1));
#pragma unroll
    for (int o = 0; o < H2; o++) hrow[CIN + 1 + o] = z3[o];
}

// ============================================================
// Sig1: chunk sums + exclusive prefix (s1 never materialized)
// ============================================================
__global__ __launch_bounds__(512) void k_sig1_sum() {
    __shared__ float hs[CH1 + 1][C1];
    int b = blockIdx.y, nc = blockIdx.x, tid = threadIdx.x;
    int c0 = nc * CH1;
    for (int idx = tid; idx < (CH1 + 1) * C1; idx += 512) {
        int r = idx / C1, c = idx - r * C1;
        int row = c0 - 1 + r;
        hs[r][c] = (row >= 0 && row < L1) ? g_h[(size_t)(b * L1 + row) * C1 + c] : 0.f;
    }
    __syncthreads();
    if (tid >= C1 * C1) return;
    int i = tid / C1, j = tid - i * C1;
    float acc = 0.f;
    int tend = min(c0 + CH1, L1);
    for (int t = c0; t < tend; t++) {
        int r = t - c0 + 1;
        float hpi = hs[r-1][i], hpj = hs[r-1][j];
        float dxi = hs[r][i] - hpi, dxj = hs[r][j] - hpj;
        acc += hpi * dxj + 0.5f * dxi * dxj;
    }
    g_csum[(b * NC1 + nc) * SC1P + tid] = acc;
}

__global__ void k_sig1_prefix() {
    int b = blockIdx.x, tid = threadIdx.x;
    if (tid >= C1 * C1) return;
    float run = 0.f;
    for (int nc = 0; nc < NC1; nc++) {
        int idx = (b * NC1 + nc) * SC1P + tid;
        float v = g_csum[idx];
        g_csum[idx] = run;
        run += v;
    }
}

// ============================================================
// Conv stack 2: split-bf16 HMMA; A tile rebuilt in-kernel by a
// chunk-offset scan over h; B cp.async dbl-buf; ldmatrix; epilogue.
// ============================================================
__global__ __launch_bounds__(256, 2) void k_conv2_mma(
    const float* __restrict__ b0,
    const float* __restrict__ w1, const float* __restrict__ b1,
    const float* __restrict__ w2, const float* __restrict__ b2)
{
    extern __shared__ __align__(16) char dsm[];
    uint32_t sb = smem_u32(dsm);
    int tid = threadIdx.x;
    int lane = tid & 31, wid = tid >> 5;
    int warp_m = wid & 3, warp_n = wid >> 2;
    int b = blockIdx.y, t0 = blockIdx.x * 128;
    int g = lane >> 2, t4 = lane & 3;

    float* Hs = (float*)(dsm + OFF_H);    // Hs[r] = h[t0-1+r], 132 rows

    float C[2][4][4];
#pragma unroll
    for (int mt = 0; mt < 2; mt++)
#pragma unroll
        for (int nt = 0; nt < 4; nt++)
#pragma unroll
            for (int q = 0; q < 4; q++) C[mt][nt][q] = 0.f;

    uint32_t aoff = (uint32_t)((lane & 15) * 144 + (lane >> 4) * 16);
    int q = lane >> 3, rr = lane & 7;
    uint32_t boff = (uint32_t)((((q >> 1) * 8) + rr) * 144 + (q & 1) * 16);

#define ISSUE_B(ph_, bbuf_) do {                                            \
        int cbB_ = (ph_) >> 2, kkB_ = (ph_) & 3;                            \
        int cbbB_ = cbB_ << 6;                                              \
        _Pragma("unroll")                                                   \
        for (int it = 0; it < 2; it++) {                                    \
            int idx_ = tid + it * 256;                                      \
            int o_ = idx_ >> 3, g8_ = idx_ & 7;                             \
            uint32_t d_ = sb + (bbuf_) + (uint32_t)(o_ * 144 + g8_ * 16);   \
            cp16(d_, g_wbh + (size_t)(kkB_ * 64 + o_) * SC1P + cbbB_ + g8_ * 8, 16u); \
            cp16(d_ + BBUF_LO, g_wbl + (size_t)(kkB_ * 64 + o_) * SC1P + cbbB_ + g8_ * 8, 16u); \
        }                                                                   \
    } while (0)

    auto do_scan = [&](int cb) {
        int ch = tid & 63, seg = tid >> 6;
        if (seg >= 3) return;
        int gch = cb * 64 + ch;
        int r0 = seg << 6;
        int rend = (seg == 2) ? 131 : (r0 + 64);
        char* hp_dst = dsm + OFF_A + (uint32_t)ch * 2;
        char* lo_dst = dsm + OFF_A + ABUF_LO + (uint32_t)ch * 2;
        if (gch < C1) {
            for (int r = r0; r < rend; r++) {
                float v = (t0 + r < L1) ? Hs[(r + 1) * C1 + gch] : 0.f;
                __nv_bfloat16 h16 = __float2bfloat16(v);
                __nv_bfloat16 l16 = __float2bfloat16(v - __bfloat162float(h16));
                *(__nv_bfloat16*)(hp_dst + r * 144) = h16;
                *(__nv_bfloat16*)(lo_dst + r * 144) = l16;
            }
        } else if (gch < SIGC1) {
            int p = gch - C1;
            int i = p / C1, j = p - i * C1;
            int chunk = (t0 >> 6) + seg;
            float acc = (chunk < NC1)
                ? g_csum[((size_t)b * NC1 + chunk) * SC1P + p] : 0.f;
            float hpi = Hs[r0 * C1 + i], hpj = Hs[r0 * C1 + j];
            for (int r = r0; r < rend; r++) {
                float hni = Hs[(r + 1) * C1 + i], hnj = Hs[(r + 1) * C1 + j];
                float dxi = hni - hpi, dxj = hnj - hpj;
                acc += hpi * dxj + 0.5f * dxi * dxj;
                float v = (t0 + r < L1) ? acc : 0.f;
                __nv_bfloat16 h16 = __float2bfloat16(v);
                __nv_bfloat16 l16 = __float2bfloat16(v - __bfloat162float(h16));
                *(__nv_bfloat16*)(hp_dst + r * 144) = h16;
                *(__nv_bfloat16*)(lo_dst + r * 144) = l16;
                hpi = hni; hpj = hnj;
            }
        } else {
            __nv_bfloat16 z = __float2bfloat16(0.f);
            for (int r = r0; r < rend; r++) {
                *(__nv_bfloat16*)(hp_dst + r * 144) = z;
                *(__nv_bfloat16*)(lo_dst + r * 144) = z;
            }
        }
    };

    // ---- prologue: H rows + B(0) ----
    for (int idx = tid; idx < 132 * C1; idx += 256) {
        int r = idx / C1, c = idx - r * C1;
        int trow = t0 - 1 + r;
        Hs[idx] = (trow >= 0 && trow < L1)
            ? g_h[((size_t)b * L1 + trow) * C1 + c] : 0.f;
    }
    ISSUE_B(0, BBUF(0));
    cp_commit();
    __syncthreads();              // H visible
    do_scan(0);                   // A(cb=0)

    for (int p = 0; p < 32; p++) {
        int kk = p & 3;
        if (p < 31) {
            ISSUE_B(p + 1, BBUF((p + 1) & 1));
            cp_commit();
            cp_wait1();
        } else {
            cp_wait0();
        }
        __syncthreads();          // publishes scan stores + B(p); fences WAR

        uint32_t Ah = sb + OFF_A + (uint32_t)((kk + warp_m * 32) * 144) + aoff;
        uint32_t Bb = sb + BBUF(p & 1) + (uint32_t)(warp_n * 32 * 144) + boff;
#pragma unroll
        for (int ks = 0; ks < 4; ks++) {
            uint32_t ko = (uint32_t)(ks * 32);
            uint32_t ah[2][4], al[2][4], bh[4][2], bl[4][2];
#pragma unroll
            for (int mt = 0; mt < 2; mt++) {
                ldm_x4(ah[mt][0], ah[mt][1], ah[mt][2], ah[mt][3],
                       Ah + (uint32_t)(mt * 16 * 144) + ko);
                ldm_x4(al[mt][0], al[mt][1], al[mt][2], al[mt][3],
                       Ah + ABUF_LO + (uint32_t)(mt * 16 * 144) + ko);
            }
#pragma unroll
            for (int j2 = 0; j2 < 2; j2++) {
                ldm_x4(bh[2*j2][0], bh[2*j2][1], bh[2*j2+1][0], bh[2*j2+1][1],
                       Bb + (uint32_t)(j2 * 16 * 144) + ko);
                ldm_x4(bl[2*j2][0], bl[2*j2][1], bl[2*j2+1][0], bl[2*j2+1][1],
                       Bb + BBUF_LO + (uint32_t)(j2 * 16 * 144) + ko);
            }
#pragma unroll
            for (int mt = 0; mt < 2; mt++)
#pragma unroll
                for (int nt = 0; nt < 4; nt++) {
                    float* c = C[mt][nt];
                    mma_bf16(c[0], c[1], c[2], c[3],
                             ah[mt][0], ah[mt][1], ah[mt][2], ah[mt][3],
                             bh[nt][0], bh[nt][1]);
                    mma_bf16(c[0], c[1], c[2], c[3],
                             ah[mt][0], ah[mt][1], ah[mt][2], ah[mt][3],
                             bl[nt][0], bl[nt][1]);
                    mma_bf16(c[0], c[1], c[2], c[3],
                             al[mt][0], al[mt][1], al[mt][2], al[mt][3],
                             bh[nt][0], bh[nt][1]);
                }
        }
        __syncthreads();          // all reads of A(cb)/B(p) done (WAR fence)
        if (kk == 3 && p < 31) do_scan((p >> 2) + 1);
    }

    // ---- epilogue ----
#pragma unroll
    for (int mt = 0; mt < 2; mt++)
#pragma unroll
        for (int nt = 0; nt < 4; nt++) {
            int row = warp_m * 32 + mt * 16 + g;
            int col = warp_n * 32 + nt * 8 + 2 * t4;
            *(float2*)(dsm + OFF_Z + row * 272 + col * 4) =
                make_float2(C[mt][nt][0], C[mt][nt][1]);
            *(float2*)(dsm + OFF_Z + (row + 8) * 272 + col * 4) =
                make_float2(C[mt][nt][2], C[mt][nt][3]);
        }
    float* W1t = (float*)(dsm + OFF_W1);
    float* W2s = (float*)(dsm + OFF_W2);
    float* bss = (float*)(dsm + OFF_BS);
#pragma unroll
    for (int qq = 0; qq < 16; qq++) {
        int idx = tid + qq * 256;
        W1t[(idx & 63) * 64 + (idx >> 6)] = w1[idx];
    }
#pragma unroll
    for (int qq = 0; qq < 4; qq++) {
        int idx = tid + qq * 256;
        W2s[idx] = w2[idx];
    }
    if (tid < 64) { bss[tid] = b0[tid]; bss[64 + tid] = b1[tid]; }
    if (tid < 16) bss[128 + tid] = b2[tid];
    __syncthreads();

    int row = tid >> 1, half = tid & 1;
    int o2b = half * 32;
    float z2[32];
#pragma unroll
    for (int o = 0; o < 32; o++) z2[o] = bss[64 + o2b + o];
#pragma unroll 4
    for (int c = 0; c < 64; c++) {
        float zc = fmaxf(*(const float*)(dsm + OFF_Z + row * 272 + c * 4) + bss[c], 0.f);
        const float4* wv = (const float4*)&W1t[c * 64 + o2b];
#pragma unroll
        for (int q8 = 0; q8 < 8; q8++) {
            float4 w4 = wv[q8];
            z2[q8*4+0] += zc * w4.x; z2[q8*4+1] += zc * w4.y;
            z2[q8*4+2] += zc * w4.z; z2[q8*4+3] += zc * w4.w;
        }
    }
#pragma unroll
    for (int o = 0; o < 32; o++) z2[o] = fmaxf(z2[o], 0.f);

    float pv[16];
#pragma unroll
    for (int o3 = 0; o3 < 16; o3++) {
        float s = 0.f;
        const float4* wv = (const float4*)&W2s[o3 * 64 + o2b];
#pragma unroll
        for (int q8 = 0; q8 < 8; q8++) {
            float4 w4 = wv[q8];
            s += w4.x * z2[q8*4+0] + w4.y * z2[q8*4+1]
               + w4.z * z2[q8*4+2] + w4.w * z2[q8*4+3];
        }
        pv[o3] = s;
    }
#pragma unroll
    for (int o3 = 0; o3 < 16; o3++)
        pv[o3] += __shfl_xor_sync(0xffffffffu, pv[o3], 1);

    int t = t0 + row;
    if (t < L2) {
        int ob = half * 8;
        float4 v0 = make_float4(pv[ob+0] + bss[128+ob+0], pv[ob+1] + bss[128+ob+1],
                                pv[ob+2] + bss[128+ob+2], pv[ob+3] + bss[128+ob+3]);
        float4 v1 = make_float4(pv[ob+4] + bss[128+ob+4], pv[ob+5] + bss[128+ob+5],
                                pv[ob+6] + bss[128+ob+6], pv[ob+7] + bss[128+ob+7]);
        float* dst = &g_h2[(size_t)(b * L2 + t) * H2 + ob];
        *(float4*)dst = v0;
        *(float4*)(dst + 4) = v1;
    }
}

// ============================================================
// become_constant + sig2 + linear
// ============================================================
__global__ __launch_bounds__(256) void k_sig2(
    const int* __restrict__ lengths,
    const float* __restrict__ lw, const float* __restrict__ lb,
    float* __restrict__ out)
{
    __shared__ float hs[129][16];
    __shared__ float s2s[SIGC2];
    int b = blockIdx.x, tid = threadIdx.x;
    int adj = lengths[b] - 2 * KS + 2;
    if (adj < 1) adj = 1;
    if (adj > L2) adj = L2;
    int i = tid >> 4, j = tid & 15;
    float acc = 0.f;
    for (int c0 = 0; c0 < adj; c0 += 128) {
        for (int idx = tid; idx < 129 * 16; idx += 256) {
            int r = idx >> 4, c = idx & 15;
            int row = c0 - 1 + r;
            hs[r][c] = (row >= 0 && row < L2) ? g_h2[(size_t)(b * L2 + row) * H2 + c] : 0.f;
        }
        __syncthreads();
        int tend = min(c0 + 128, adj);
        for (int t = c0; t < tend; t++) {
            int r = t - c0 + 1;
            float hpi = hs[r-1][i], hpj = hs[r-1][j];
            float dxi = hs[r][i] - hpi, dxj = hs[r][j] - hpj;
            acc += hpi * dxj + 0.5f * dxi * dxj;
        }
        __syncthreads();
    }
    s2s[16 + tid] = acc;
    if (tid < 16) s2s[tid] = g_h2[(size_t)(b * L2 + adj - 1) * H2 + tid];
    __syncthreads();
    if (tid < OUTC) {
        float v = lb[tid];
        for (int c = 0; c < SIGC2; c++) v += lw[tid * SIGC2 + c] * s2s[c];
        out[b * OUTC + tid] = v;
    }
}

// ============================================================
extern "C" void kernel_launch(void* const* d_in, const int* in_sizes, int n_in,
                              void* d_out, int out_size) {
    const float* x      = (const float*)d_in[0];
    const int*   lens   = (const int*)  d_in[1];
    const float* a1_w0  = (const float*)d_in[2];
    const float* a1_b0  = (const float*)d_in[3];
    const float* a1_w1  = (const float*)d_in[4];
    const float* a1_b1  = (const float*)d_in[5];
    const float* a1_w2  = (const float*)d_in[6];
    const float* a1_b2  = (const float*)d_in[7];
    const float* a2_w0  = (const float*)d_in[8];
    const float* a2_b0  = (const float*)d_in[9];
    const float* a2_w1  = (const float*)d_in[10];
    const float* a2_b1  = (const float*)d_in[11];
    const float* a2_w2  = (const float*)d_in[12];
    const float* a2_b2  = (const float*)d_in[13];
    const float* lin_w  = (const float*)d_in[14];
    const float* lin_b  = (const float*)d_in[15];
    float* out = (float*)d_out;

    static bool attr_set = false;
    if (!attr_set) {
        cudaFuncSetAttribute(k_conv2_mma, cudaFuncAttributeMaxDynamicSharedMemorySize, DSMB);
        attr_set = true;
    }

    k_repack<<<512, 256>>>(a2_w0);
    k_aug1<<<dim3(8, B_), 128>>>(x, a1_w0, a1_b0, a1_w1, a1_b1, a1_w2, a1_b2);
    k_sig1_sum<<<dim3(NC1, B_), 512>>>();
    k_sig1_prefix<<<B_, 512>>>();
    k_conv2_mma<<<dim3(8, B_), 256, DSMB>>>(a2_b0, a2_w1, a2_b1, a2_w2, a2_b2);
    k_sig2<<<B_, 256>>>(lens, lin_w, lin_b, out);
}